// round 3
// baseline (speedup 1.0000x reference)
#include <cuda_runtime.h>

typedef unsigned long long ULL;

// ---- packed f32x2 helpers (Blackwell sm_103a): ptxas never emits FFMA2 from C++ ----
__device__ __forceinline__ ULL f2_pack(float x, float y) {
    ULL r;
    asm("mov.b64 %0, {%1,%2};" : "=l"(r)
        : "r"(__float_as_uint(x)), "r"(__float_as_uint(y)));
    return r;
}
__device__ __forceinline__ void f2_unpack(ULL a, float& x, float& y) {
    unsigned lo, hi;
    asm("mov.b64 {%0,%1}, %2;" : "=r"(lo), "=r"(hi) : "l"(a));
    x = __uint_as_float(lo);
    y = __uint_as_float(hi);
}
__device__ __forceinline__ ULL f2_fma(ULL a, ULL b, ULL c) {
    ULL d;
    asm("fma.rn.f32x2 %0, %1, %2, %3;" : "=l"(d) : "l"(a), "l"(b), "l"(c));
    return d;
}
__device__ __forceinline__ ULL f2_mul(ULL a, ULL b) {
    ULL d;
    asm("mul.rn.f32x2 %0, %1, %2;" : "=l"(d) : "l"(a), "l"(b));
    return d;
}

// ---- problem constants (fixed shapes) ----
constexpr int B = 2, H = 16, S = 4096, D = 64;
constexpr int BH = B * H;
constexpr int WIN = 512;      // sliding window (inclusive of self)
constexpr int GQ = 64;        // global-prefix queries
constexpr int MT = 256;       // queries per banded block (8 warps -> 2/SMSP)
constexpr int CK = 64;        // keys per smem chunk
constexpr int NCH = (WIN + MT) / CK;  // 12 chunks cover [qs-512, qs+255]
constexpr float SCALE = 0.125f;   // 1/sqrt(64)
constexpr float NEGV = -1e9f;

constexpr int SPLITS = 16;
constexpr int KPS = S / SPLITS;   // 256 keys per split

// scratch for split-K global prefix (device globals: no allocation allowed)
__device__ float g_pm[BH][SPLITS][GQ];
__device__ float g_pl[BH][SPLITS][GQ];
__device__ float g_pacc[BH][SPLITS][GQ][D];

// shared inner step: 16 keys -> scores, online softmax, PV accumulate.
// All smem reads are float4 (LDS.128): 2 FFMA2 per LDS.
template <bool MASKED>
__device__ __forceinline__ void attend16(
    const float* __restrict__ Ks, const float* __restrict__ Vs,
    const ULL* __restrict__ qreg, ULL* __restrict__ acc,
    float& m, float& l, int j0, int i, int gg) {
    float s[16];
#pragma unroll
    for (int c = 0; c < 16; ++c) {
        const int kc = gg * 16 + c;
        const float4* kr = (const float4*)(Ks + kc * D);
        ULL dp0 = 0ULL, dp1 = 0ULL;
#pragma unroll
        for (int t = 0; t < 16; ++t) {
            float4 a = kr[t];
            dp0 = f2_fma(qreg[2 * t],     f2_pack(a.x, a.y), dp0);
            dp1 = f2_fma(qreg[2 * t + 1], f2_pack(a.z, a.w), dp1);
        }
        float x0, y0, x1, y1;
        f2_unpack(dp0, x0, y0);
        f2_unpack(dp1, x1, y1);
        float sc = ((x0 + x1) + (y0 + y1)) * SCALE;
        if (MASKED) {
            int j = j0 + kc;
            bool valid = (j <= i) && (j >= i - (WIN - 1));  // j>=0 by chunk skipping
            s[c] = valid ? sc : NEGV;
        } else {
            s[c] = sc;
        }
    }
    float mn = m;
#pragma unroll
    for (int c = 0; c < 16; ++c) mn = fmaxf(mn, s[c]);
    if (mn > m) {
        float corr = __expf(m - mn);
        l *= corr;
        ULL c2 = f2_pack(corr, corr);
#pragma unroll
        for (int d = 0; d < 32; ++d) acc[d] = f2_mul(acc[d], c2);
        m = mn;
    }
#pragma unroll
    for (int c = 0; c < 16; ++c) {
        float p = __expf(s[c] - m);
        l += p;
        ULL p2 = f2_pack(p, p);
        const float4* vr = (const float4*)(Vs + (gg * 16 + c) * D);
#pragma unroll
        for (int t = 0; t < 16; ++t) {
            float4 a = vr[t];
            acc[2 * t]     = f2_fma(p2, f2_pack(a.x, a.y), acc[2 * t]);
            acc[2 * t + 1] = f2_fma(p2, f2_pack(a.z, a.w), acc[2 * t + 1]);
        }
    }
}

// =====================================================================
// Kernel 1: banded (sliding-window causal) flash attention.
// One query per lane -> all LDS from K/V smem rows are warp-broadcast.
// 256 threads/CTA -> 2 warps per SMSP for latency hiding.
// =====================================================================
__global__ void __launch_bounds__(MT, 1)
swa_banded(const float* __restrict__ q, const float* __restrict__ k,
           const float* __restrict__ v, float* __restrict__ out) {
    __shared__ float Ks[CK * D];
    __shared__ float Vs[CK * D];

    const int bh = blockIdx.y;
    const int qs = blockIdx.x * MT;
    const int r = threadIdx.x;
    const int i = qs + r;                     // global query position
    const size_t base = (size_t)bh * S * D;

    // q row in registers as 32 f32x2
    ULL qreg[32];
    {
        const float4* qp = (const float4*)(q + base + (size_t)i * D);
#pragma unroll
        for (int t = 0; t < 16; ++t) {
            float4 x = qp[t];
            qreg[2 * t]     = f2_pack(x.x, x.y);
            qreg[2 * t + 1] = f2_pack(x.z, x.w);
        }
    }

    ULL acc[32];
#pragma unroll
    for (int d = 0; d < 32; ++d) acc[d] = 0ULL;
    float m = NEGV, l = 0.f;

    // keys needed: [max(0, qs-511), qs+255].
    // chunks of 64 from qs-512; skip chunks that are entirely j<0.
    const int ch0 = (qs >= WIN) ? 0 : (WIN - qs) / CK;

#pragma unroll 1
    for (int ch = ch0; ch < NCH; ++ch) {
        const int j0 = qs - WIN + ch * CK;    // >= 0 guaranteed by ch0

        __syncthreads();
        // cooperative load: CK*D floats = 1024 float4 per array, 4 per thread
#pragma unroll
        for (int t = 0; t < 4; ++t) {
            int idx = threadIdx.x + t * MT;   // 0..1023
            int row = idx >> 4;
            int c4 = idx & 15;
            int j = j0 + row;
            *(float4*)(Ks + row * D + c4 * 4) =
                *(const float4*)(k + base + (size_t)j * D + c4 * 4);
            *(float4*)(Vs + row * D + c4 * 4) =
                *(const float4*)(v + base + (size_t)j * D + c4 * 4);
        }
        __syncthreads();

#pragma unroll 1
        for (int gg = 0; gg < CK / 16; ++gg)
            attend16<true>(Ks, Vs, qreg, acc, m, l, j0, i, gg);
    }

    const float inv = 1.f / l;
    float2* op = (float2*)(out + base + (size_t)i * D);
#pragma unroll
    for (int d = 0; d < 32; ++d) {
        float x, y;
        f2_unpack(acc[d], x, y);
        op[d] = make_float2(x * inv, y * inv);
    }
}

// =====================================================================
// Kernel 2: global prefix (first GQ queries attend ALL keys), split-K.
// grid (SPLITS, BH), 64 threads = 64 queries; writes partials.
// =====================================================================
__global__ void __launch_bounds__(GQ, 1)
swa_global(const float* __restrict__ q, const float* __restrict__ k,
           const float* __restrict__ v) {
    __shared__ float Ks[CK * D];
    __shared__ float Vs[CK * D];

    const int bh = blockIdx.y;
    const int sp = blockIdx.x;
    const int qi = threadIdx.x;               // 0..63
    const size_t base = (size_t)bh * S * D;

    ULL qreg[32];
    {
        const float4* qp = (const float4*)(q + base + (size_t)qi * D);
#pragma unroll
        for (int t = 0; t < 16; ++t) {
            float4 x = qp[t];
            qreg[2 * t]     = f2_pack(x.x, x.y);
            qreg[2 * t + 1] = f2_pack(x.z, x.w);
        }
    }
    ULL acc[32];
#pragma unroll
    for (int d = 0; d < 32; ++d) acc[d] = 0ULL;
    float m = NEGV, l = 0.f;

    const int k0 = sp * KPS;
#pragma unroll 1
    for (int ch = 0; ch < KPS / CK; ++ch) {
        const int j0 = k0 + ch * CK;

        __syncthreads();
#pragma unroll
        for (int t = 0; t < 16; ++t) {
            int idx = threadIdx.x + t * GQ;   // 0..1023
            int row = idx >> 4;
            int c4 = idx & 15;
            int j = j0 + row;
            *(float4*)(Ks + row * D + c4 * 4) =
                *(const float4*)(k + base + (size_t)j * D + c4 * 4);
            *(float4*)(Vs + row * D + c4 * 4) =
                *(const float4*)(v + base + (size_t)j * D + c4 * 4);
        }
        __syncthreads();

#pragma unroll 1
        for (int gg = 0; gg < CK / 16; ++gg)
            attend16<false>(Ks, Vs, qreg, acc, m, l, j0, qi, gg);
    }

    g_pm[bh][sp][qi] = m;
    g_pl[bh][sp][qi] = l;
    float2* ap = (float2*)&g_pacc[bh][sp][qi][0];
#pragma unroll
    for (int d = 0; d < 32; ++d) {
        float x, y;
        f2_unpack(acc[d], x, y);
        ap[d] = make_float2(x, y);
    }
}

// =====================================================================
// Kernel 3: combine split-K partials, overwrite rows [0, GQ)
// grid (GQ, BH), D threads
// =====================================================================
__global__ void __launch_bounds__(D, 1)
swa_combine(float* __restrict__ out) {
    const int bh = blockIdx.y;
    const int qi = blockIdx.x;
    const int d = threadIdx.x;

    float M = -1e30f;
#pragma unroll
    for (int s = 0; s < SPLITS; ++s) M = fmaxf(M, g_pm[bh][s][qi]);
    float den = 0.f, num = 0.f;
#pragma unroll
    for (int s = 0; s < SPLITS; ++s) {
        float w = __expf(g_pm[bh][s][qi] - M);
        den += w * g_pl[bh][s][qi];
        num += w * g_pacc[bh][s][qi][d];
    }
    out[(size_t)bh * S * D + (size_t)qi * D + d] = num / den;
}

// =====================================================================
extern "C" void kernel_launch(void* const* d_in, const int* in_sizes, int n_in,
                              void* d_out, int out_size) {
    const float* q = (const float*)d_in[0];
    const float* k = (const float*)d_in[1];
    const float* v = (const float*)d_in[2];
    float* out = (float*)d_out;
    (void)in_sizes; (void)n_in; (void)out_size;

    dim3 g1(S / MT, BH);
    swa_banded<<<g1, MT>>>(q, k, v, out);

    dim3 g2(SPLITS, BH);
    swa_global<<<g2, GQ>>>(q, k, v);

    dim3 g3(GQ, BH);
    swa_combine<<<g3, D>>>(out);
}

// round 4
// speedup vs baseline: 1.1797x; 1.1797x over previous
#include <cuda_runtime.h>

typedef unsigned long long ULL;

// ---- packed f32x2 helpers (Blackwell sm_103a) ----
__device__ __forceinline__ ULL f2_pack(float x, float y) {
    ULL r;
    asm("mov.b64 %0, {%1,%2};" : "=l"(r)
        : "r"(__float_as_uint(x)), "r"(__float_as_uint(y)));
    return r;
}
__device__ __forceinline__ void f2_unpack(ULL a, float& x, float& y) {
    unsigned lo, hi;
    asm("mov.b64 {%0,%1}, %2;" : "=r"(lo), "=r"(hi) : "l"(a));
    x = __uint_as_float(lo);
    y = __uint_as_float(hi);
}
__device__ __forceinline__ ULL f2_fma(ULL a, ULL b, ULL c) {
    ULL d;
    asm("fma.rn.f32x2 %0, %1, %2, %3;" : "=l"(d) : "l"(a), "l"(b), "l"(c));
    return d;
}
__device__ __forceinline__ ULL f2_mul(ULL a, ULL b) {
    ULL d;
    asm("mul.rn.f32x2 %0, %1, %2;" : "=l"(d) : "l"(a), "l"(b));
    return d;
}

// ---- problem constants (fixed shapes) ----
constexpr int B = 2, H = 16, S = 4096, D = 64;
constexpr int BH = B * H;
constexpr int WIN = 512;          // sliding window (inclusive of self)
constexpr int GQ = 64;            // global-prefix queries
constexpr int NT = 128;           // threads per banded CTA
constexpr int QB = 128;           // queries per banded CTA (2 per thread, half-D each)
constexpr int CK = 64;            // keys per smem chunk
constexpr int NCH = (WIN + QB) / CK;  // 10 chunks cover [qs-512, qs+127]
constexpr float SCALE = 0.125f;   // 1/sqrt(64)
constexpr float NEGV = -1e9f;

constexpr int SPLITS = 16;
constexpr int KPS = S / SPLITS;   // 256 keys per split

// scratch for split-K global prefix (device globals: no allocation allowed)
__device__ float g_pm[BH][SPLITS][GQ];
__device__ float g_pl[BH][SPLITS][GQ];
__device__ float g_pacc[BH][SPLITS][GQ][D];

// =====================================================================
// Kernel 1: banded (sliding-window causal) flash attention.
// Lane pairs: thread (p,h) handles queries {qs+p, qs+64+p}, d-half h.
// K/V half-rows loaded once per key, reused for BOTH queries ->
// smem return bytes per query*key halved vs 1-query-per-lane.
// =====================================================================
__global__ void __launch_bounds__(NT, 2)
swa_banded(const float* __restrict__ q, const float* __restrict__ k,
           const float* __restrict__ v, float* __restrict__ out) {
    __shared__ float Ks[CK * D];
    __shared__ float Vs[CK * D];

    const int bh = blockIdx.y;
    const int qs = blockIdx.x * QB;
    const int p = threadIdx.x >> 1;        // pair index 0..63
    const int h = threadIdx.x & 1;         // d-half 0/1
    const int iA = qs + p;                 // query A
    const int iB = qs + 64 + p;            // query B
    const size_t base = (size_t)bh * S * D;

    // q half-rows in registers: 16 ULL each
    ULL qA[16], qB[16];
    {
        const float4* pa = (const float4*)(q + base + (size_t)iA * D + h * 32);
        const float4* pb = (const float4*)(q + base + (size_t)iB * D + h * 32);
#pragma unroll
        for (int t = 0; t < 8; ++t) {
            float4 a = pa[t], b = pb[t];
            qA[2 * t] = f2_pack(a.x, a.y); qA[2 * t + 1] = f2_pack(a.z, a.w);
            qB[2 * t] = f2_pack(b.x, b.y); qB[2 * t + 1] = f2_pack(b.z, b.w);
        }
    }

    ULL accA[16], accB[16];
#pragma unroll
    for (int t = 0; t < 16; ++t) { accA[t] = 0ULL; accB[t] = 0ULL; }
    float mA = NEGV, lA = 0.f, mB = NEGV, lB = 0.f;

    const int ch0 = (qs >= WIN) ? 0 : (WIN - qs) / CK;

#pragma unroll 1
    for (int ch = ch0; ch < NCH; ++ch) {
        const int j0 = qs - WIN + ch * CK;   // >= 0 guaranteed by ch0

        __syncthreads();
        // cooperative load: 64 rows x 16 float4 per array, 8 per thread
#pragma unroll
        for (int t = 0; t < 8; ++t) {
            int idx = threadIdx.x + t * NT;  // 0..1023
            int row = idx >> 4;
            int c4 = idx & 15;
            int j = j0 + row;
            *(float4*)(Ks + row * D + c4 * 4) =
                *(const float4*)(k + base + (size_t)j * D + c4 * 4);
            *(float4*)(Vs + row * D + c4 * 4) =
                *(const float4*)(v + base + (size_t)j * D + c4 * 4);
        }
        __syncthreads();

#pragma unroll 1
        for (int g = 0; g < CK / 8; ++g) {
            float sA[8], sB[8];
            // ---- scores for 8 keys ----
#pragma unroll
            for (int c = 0; c < 8; ++c) {
                const int kc = g * 8 + c;
                const ULL* kr = (const ULL*)(Ks + kc * D) + h * 16;
                ULL a0 = 0ULL, a1 = 0ULL, b0 = 0ULL, b1 = 0ULL;
#pragma unroll
                for (int t = 0; t < 8; ++t) {
                    ULL k0 = kr[2 * t], k1 = kr[2 * t + 1];
                    a0 = f2_fma(qA[2 * t], k0, a0);
                    a1 = f2_fma(qA[2 * t + 1], k1, a1);
                    b0 = f2_fma(qB[2 * t], k0, b0);
                    b1 = f2_fma(qB[2 * t + 1], k1, b1);
                }
                float x0, y0, x1, y1;
                f2_unpack(a0, x0, y0); f2_unpack(a1, x1, y1);
                float pa = (x0 + x1) + (y0 + y1);
                f2_unpack(b0, x0, y0); f2_unpack(b1, x1, y1);
                float pb = (x0 + x1) + (y0 + y1);
                float fa = (pa + __shfl_xor_sync(0xffffffffu, pa, 1)) * SCALE;
                float fb = (pb + __shfl_xor_sync(0xffffffffu, pb, 1)) * SCALE;
                int j = j0 + kc;
                sA[c] = ((j <= iA) && (j >= iA - (WIN - 1))) ? fa : NEGV;
                sB[c] = ((j <= iB) && (j >= iB - (WIN - 1))) ? fb : NEGV;
            }
            // ---- online softmax update (A) ----
            float mnA = mA, mnB = mB;
#pragma unroll
            for (int c = 0; c < 8; ++c) { mnA = fmaxf(mnA, sA[c]); mnB = fmaxf(mnB, sB[c]); }
            if (mnA > mA) {
                float corr = __expf(mA - mnA);
                lA *= corr;
                ULL c2 = f2_pack(corr, corr);
#pragma unroll
                for (int t = 0; t < 16; ++t) accA[t] = f2_mul(accA[t], c2);
                mA = mnA;
            }
            if (mnB > mB) {
                float corr = __expf(mB - mnB);
                lB *= corr;
                ULL c2 = f2_pack(corr, corr);
#pragma unroll
                for (int t = 0; t < 16; ++t) accB[t] = f2_mul(accB[t], c2);
                mB = mnB;
            }
            // ---- PV accumulate ----
#pragma unroll
            for (int c = 0; c < 8; ++c) {
                float pAa = __expf(sA[c] - mA);
                float pBb = __expf(sB[c] - mB);
                lA += pAa; lB += pBb;
                ULL pA2 = f2_pack(pAa, pAa);
                ULL pB2 = f2_pack(pBb, pBb);
                const ULL* vr = (const ULL*)(Vs + (g * 8 + c) * D) + h * 16;
#pragma unroll
                for (int t = 0; t < 16; ++t) {
                    ULL vv = vr[t];
                    accA[t] = f2_fma(pA2, vv, accA[t]);
                    accB[t] = f2_fma(pB2, vv, accB[t]);
                }
            }
        }
    }

    // ---- write both query half-rows ----
    {
        float inv = 1.f / lA;
        float4* op = (float4*)(out + base + (size_t)iA * D + h * 32);
#pragma unroll
        for (int t = 0; t < 8; ++t) {
            float x0, y0, x1, y1;
            f2_unpack(accA[2 * t], x0, y0);
            f2_unpack(accA[2 * t + 1], x1, y1);
            op[t] = make_float4(x0 * inv, y0 * inv, x1 * inv, y1 * inv);
        }
    }
    {
        float inv = 1.f / lB;
        float4* op = (float4*)(out + base + (size_t)iB * D + h * 32);
#pragma unroll
        for (int t = 0; t < 8; ++t) {
            float x0, y0, x1, y1;
            f2_unpack(accB[2 * t], x0, y0);
            f2_unpack(accB[2 * t + 1], x1, y1);
            op[t] = make_float4(x0 * inv, y0 * inv, x1 * inv, y1 * inv);
        }
    }
}

// =====================================================================
// Kernel 2: global prefix (first GQ queries attend ALL keys), split-K.
// grid (SPLITS, BH), 64 threads = 64 queries; writes partials.
// =====================================================================
__global__ void __launch_bounds__(GQ, 1)
swa_global(const float* __restrict__ q, const float* __restrict__ k,
           const float* __restrict__ v) {
    __shared__ float Ks[CK * D];
    __shared__ float Vs[CK * D];

    const int bh = blockIdx.y;
    const int sp = blockIdx.x;
    const int qi = threadIdx.x;               // 0..63
    const size_t base = (size_t)bh * S * D;

    ULL qreg[32];
    {
        const float4* qp = (const float4*)(q + base + (size_t)qi * D);
#pragma unroll
        for (int t = 0; t < 16; ++t) {
            float4 x = qp[t];
            qreg[2 * t] = f2_pack(x.x, x.y);
            qreg[2 * t + 1] = f2_pack(x.z, x.w);
        }
    }
    ULL acc[32];
#pragma unroll
    for (int d = 0; d < 32; ++d) acc[d] = 0ULL;
    float m = NEGV, l = 0.f;

    const int k0 = sp * KPS;
#pragma unroll 1
    for (int ch = 0; ch < KPS / CK; ++ch) {
        const int j0 = k0 + ch * CK;

        __syncthreads();
#pragma unroll
        for (int t = 0; t < 16; ++t) {
            int idx = threadIdx.x + t * GQ;   // 0..1023
            int row = idx >> 4;
            int c4 = idx & 15;
            int j = j0 + row;
            *(float4*)(Ks + row * D + c4 * 4) =
                *(const float4*)(k + base + (size_t)j * D + c4 * 4);
            *(float4*)(Vs + row * D + c4 * 4) =
                *(const float4*)(v + base + (size_t)j * D + c4 * 4);
        }
        __syncthreads();

#pragma unroll 1
        for (int g = 0; g < CK / 16; ++g) {
            float s[16];
#pragma unroll
            for (int c = 0; c < 16; ++c) {
                const ULL* kr = (const ULL*)(Ks + (g * 16 + c) * D);
                ULL dp0 = 0ULL, dp1 = 0ULL;
#pragma unroll
                for (int t = 0; t < 16; ++t) {
                    dp0 = f2_fma(qreg[2 * t], kr[2 * t], dp0);
                    dp1 = f2_fma(qreg[2 * t + 1], kr[2 * t + 1], dp1);
                }
                float x0, y0, x1, y1;
                f2_unpack(dp0, x0, y0);
                f2_unpack(dp1, x1, y1);
                s[c] = ((x0 + x1) + (y0 + y1)) * SCALE;
            }
            float mn = m;
#pragma unroll
            for (int c = 0; c < 16; ++c) mn = fmaxf(mn, s[c]);
            if (mn > m) {
                float corr = __expf(m - mn);
                l *= corr;
                ULL c2 = f2_pack(corr, corr);
#pragma unroll
                for (int d = 0; d < 32; ++d) acc[d] = f2_mul(acc[d], c2);
                m = mn;
            }
#pragma unroll
            for (int c = 0; c < 16; ++c) {
                float pp = __expf(s[c] - m);
                l += pp;
                ULL p2 = f2_pack(pp, pp);
                const ULL* vr = (const ULL*)(Vs + (g * 16 + c) * D);
#pragma unroll
                for (int t = 0; t < 32; ++t) acc[t] = f2_fma(p2, vr[t], acc[t]);
            }
        }
    }

    g_pm[bh][sp][qi] = m;
    g_pl[bh][sp][qi] = l;
    float2* ap = (float2*)&g_pacc[bh][sp][qi][0];
#pragma unroll
    for (int d = 0; d < 32; ++d) {
        float x, y;
        f2_unpack(acc[d], x, y);
        ap[d] = make_float2(x, y);
    }
}

// =====================================================================
// Kernel 3: combine split-K partials, overwrite rows [0, GQ)
// =====================================================================
__global__ void __launch_bounds__(D, 1)
swa_combine(float* __restrict__ out) {
    const int bh = blockIdx.y;
    const int qi = blockIdx.x;
    const int d = threadIdx.x;

    float M = -1e30f;
#pragma unroll
    for (int s = 0; s < SPLITS; ++s) M = fmaxf(M, g_pm[bh][s][qi]);
    float den = 0.f, num = 0.f;
#pragma unroll
    for (int s = 0; s < SPLITS; ++s) {
        float w = __expf(g_pm[bh][s][qi] - M);
        den += w * g_pl[bh][s][qi];
        num += w * g_pacc[bh][s][qi][d];
    }
    out[(size_t)bh * S * D + (size_t)qi * D + d] = num / den;
}

// =====================================================================
extern "C" void kernel_launch(void* const* d_in, const int* in_sizes, int n_in,
                              void* d_out, int out_size) {
    const float* q = (const float*)d_in[0];
    const float* k = (const float*)d_in[1];
    const float* v = (const float*)d_in[2];
    float* out = (float*)d_out;
    (void)in_sizes; (void)n_in; (void)out_size;

    dim3 g1(S / QB, BH);
    swa_banded<<<g1, NT>>>(q, k, v, out);

    dim3 g2(SPLITS, BH);
    swa_global<<<g2, GQ>>>(q, k, v);

    dim3 g3(GQ, BH);
    swa_combine<<<g3, D>>>(out);
}